// round 3
// baseline (speedup 1.0000x reference)
#include <cuda_runtime.h>

#define NMAX 100000
#define EMAX 3200000
#define DD 256
#define CC 40

struct __align__(8) EdgeRec { int src; float nrm; };

// ---- static device scratch (allocation-free rule) ----
__device__ int   g_is64;
__device__ int   g_deg[NMAX];
__device__ int   g_off[NMAX + 1];
__device__ int   g_cur[NMAX];
__device__ float g_dinv[NMAX];
__device__ EdgeRec g_edges[EMAX];
__device__ float g_T [(size_t)NMAX * DD];
__device__ float g_A [(size_t)NMAX * DD];
__device__ float g_Z0[(size_t)NMAX * CC];
__device__ float g_Za[(size_t)NMAX * CC];
__device__ float g_Zb[(size_t)NMAX * CC];

// ---- dtype detection: int64 edge_index vs silently-downcast int32 ----
__global__ void k_detect(const long long* ei, int e, int n) {
    __shared__ int bad;
    if (threadIdx.x == 0) bad = 0;
    __syncthreads();
    int m = e < 2048 ? e : 2048;
    int isbad = 0;
    for (int i = threadIdx.x; i < m; i += blockDim.x) {
        long long v = ei[i];
        if (v < 0 || v >= (long long)n) isbad = 1;
    }
    if (isbad) atomicOr(&bad, 1);
    __syncthreads();
    if (threadIdx.x == 0) g_is64 = bad ? 0 : 1;
}

__global__ void k_zero_deg(int n) {
    int i = blockIdx.x * blockDim.x + threadIdx.x;
    if (i < n) g_deg[i] = 0;
}

__global__ void k_hist(const void* ei, int e) {
    int f = g_is64;
    const long long* p64 = (const long long*)ei;
    const int* p32 = (const int*)ei;
    int stride = gridDim.x * blockDim.x;
    for (int i = blockIdx.x * blockDim.x + threadIdx.x; i < e; i += stride) {
        int d = f ? (int)p64[e + i] : p32[e + i];
        atomicAdd(&g_deg[d], 1);
    }
}

__global__ void k_dinv(int n) {
    int i = blockIdx.x * blockDim.x + threadIdx.x;
    if (i < n) g_dinv[i] = rsqrtf((float)(g_deg[i] + 1));  // +1 self loop; always > 0
}

// single-block exclusive scan of g_deg -> g_off / g_cur
__global__ void k_scan(int n) {
    __shared__ int s[1024];
    int t = threadIdx.x;
    int chunk = (n + 1023) >> 10;
    int lo = t * chunk; if (lo > n) lo = n;
    int hi = lo + chunk; if (hi > n) hi = n;
    int sum = 0;
    for (int i = lo; i < hi; i++) sum += g_deg[i];
    s[t] = sum;
    __syncthreads();
    for (int off = 1; off < 1024; off <<= 1) {
        int v = 0;
        if (t >= off) v = s[t - off];
        __syncthreads();
        if (t >= off) s[t] += v;
        __syncthreads();
    }
    int run = s[t] - sum;  // exclusive prefix of this thread's chunk
    for (int i = lo; i < hi; i++) {
        g_off[i] = run; g_cur[i] = run;
        run += g_deg[i];
    }
    if (t == 0) g_off[n] = s[1023];
}

__global__ void k_fill(const void* ei, int e) {
    int f = g_is64;
    const long long* p64 = (const long long*)ei;
    const int* p32 = (const int*)ei;
    int stride = gridDim.x * blockDim.x;
    for (int i = blockIdx.x * blockDim.x + threadIdx.x; i < e; i += stride) {
        int s, d;
        if (f) { s = (int)p64[i]; d = (int)p64[e + i]; }
        else   { s = p32[i];      d = p32[e + i]; }
        int pos = atomicAdd(&g_cur[d], 1);
        EdgeRec r; r.src = s; r.nrm = g_dinv[s] * g_dinv[d];
        g_edges[pos] = r;
    }
}

// ---- SGEMM: C[M,256] = A[M,256] @ B[256,256], 128x128x8 tile, 8x8/thread ----
__global__ void __launch_bounds__(256) k_sgemm256(
    const float* __restrict__ A, const float* __restrict__ B,
    float* __restrict__ Cm, int M)
{
    __shared__ float As[8][128];
    __shared__ float Bs[8][128];
    const int tid  = threadIdx.x;
    const int trow = tid >> 4;        // 0..15
    const int tcol = tid & 15;        // 0..15
    const int aRow = tid >> 1;        // 0..127
    const int aCol = (tid & 1) * 4;   // 0 or 4
    const int bRow = tid >> 5;        // 0..7
    const int bCol = (tid & 31) * 4;  // 0..124
    const int mBase = blockIdx.y * 128;
    const int nBase = blockIdx.x * 128;
    float acc[8][8] = {};
    const bool aok = (mBase + aRow) < M;
    const float* Aptr = A + (size_t)(mBase + aRow) * DD + aCol;
    const float* Bptr = B + (size_t)bRow * DD + nBase + bCol;

    for (int k0 = 0; k0 < DD; k0 += 8) {
        float4 av = make_float4(0.f, 0.f, 0.f, 0.f);
        if (aok) av = *(const float4*)(Aptr + k0);
        As[aCol + 0][aRow] = av.x;
        As[aCol + 1][aRow] = av.y;
        As[aCol + 2][aRow] = av.z;
        As[aCol + 3][aRow] = av.w;
        *(float4*)&Bs[bRow][bCol] = *(const float4*)(Bptr + (size_t)k0 * DD);
        __syncthreads();
#pragma unroll
        for (int k = 0; k < 8; k++) {
            float4 a0 = *(const float4*)&As[k][trow * 8];
            float4 a1 = *(const float4*)&As[k][trow * 8 + 4];
            float4 b0 = *(const float4*)&Bs[k][tcol * 8];
            float4 b1 = *(const float4*)&Bs[k][tcol * 8 + 4];
            float ar[8] = {a0.x, a0.y, a0.z, a0.w, a1.x, a1.y, a1.z, a1.w};
            float br[8] = {b0.x, b0.y, b0.z, b0.w, b1.x, b1.y, b1.z, b1.w};
#pragma unroll
            for (int i = 0; i < 8; i++)
#pragma unroll
                for (int j = 0; j < 8; j++)
                    acc[i][j] = fmaf(ar[i], br[j], acc[i][j]);
        }
        __syncthreads();
    }
#pragma unroll
    for (int i = 0; i < 8; i++) {
        int r = mBase + trow * 8 + i;
        if (r < M) {
            float* cp = Cm + (size_t)r * DD + nBase + tcol * 8;
            *(float4*)cp       = make_float4(acc[i][0], acc[i][1], acc[i][2], acc[i][3]);
            *(float4*)(cp + 4) = make_float4(acc[i][4], acc[i][5], acc[i][6], acc[i][7]);
        }
    }
}

// ---- GCN propagate: out = relu(A_hat @ tin + bias). block = node, thread = feature ----
__global__ void __launch_bounds__(256) k_prop_gcn(
    const float* __restrict__ tin, const float* __restrict__ bias,
    float* __restrict__ out, int n)
{
    int i = blockIdx.x;
    int t = threadIdx.x;
    int beg = g_off[i], end = g_off[i + 1];
    float di = g_dinv[i];
    float acc0 = di * di * __ldg(&tin[(size_t)i * DD + t]);  // self loop
    float acc1 = 0.f, acc2 = 0.f, acc3 = 0.f;
    int e = beg;
    for (; e + 4 <= end; e += 4) {
        EdgeRec r0 = g_edges[e], r1 = g_edges[e + 1], r2 = g_edges[e + 2], r3 = g_edges[e + 3];
        acc0 = fmaf(r0.nrm, __ldg(&tin[(size_t)r0.src * DD + t]), acc0);
        acc1 = fmaf(r1.nrm, __ldg(&tin[(size_t)r1.src * DD + t]), acc1);
        acc2 = fmaf(r2.nrm, __ldg(&tin[(size_t)r2.src * DD + t]), acc2);
        acc3 = fmaf(r3.nrm, __ldg(&tin[(size_t)r3.src * DD + t]), acc3);
    }
    for (; e < end; e++) {
        EdgeRec r = g_edges[e];
        acc0 = fmaf(r.nrm, __ldg(&tin[(size_t)r.src * DD + t]), acc0);
    }
    float v = (acc0 + acc1) + (acc2 + acc3) + bias[t];
    out[(size_t)i * DD + t] = v > 0.f ? v : 0.f;
}

// ---- z0 = H[N,256] @ fc_w[256,40]: warp per row, W^T staged in shared ----
__global__ void __launch_bounds__(256) k_zgemm(
    const float* __restrict__ H, const float* __restrict__ W,
    float* __restrict__ Z, int n)
{
    __shared__ float wT[CC * DD];  // 40 KB, [c][k]
    for (int i = threadIdx.x; i < CC * DD; i += blockDim.x) {
        int k = i / CC, c = i - k * CC;
        wT[c * DD + k] = W[i];
    }
    __syncthreads();
    int wid = threadIdx.x >> 5, lane = threadIdx.x & 31;
    int gw = blockIdx.x * 8 + wid;
    int nw = gridDim.x * 8;
    for (int row = gw; row < n; row += nw) {
        const float* hr = H + (size_t)row * DD;
        float hv[8];
#pragma unroll
        for (int s = 0; s < 8; s++) hv[s] = __ldg(&hr[lane + 32 * s]);
        float acc[CC];
#pragma unroll
        for (int c = 0; c < CC; c++) {
            const float* wr = wT + c * DD + lane;
            float a = hv[0] * wr[0];
#pragma unroll
            for (int s = 1; s < 8; s++) a = fmaf(hv[s], wr[32 * s], a);
            acc[c] = a;
        }
#pragma unroll
        for (int off = 16; off; off >>= 1)
#pragma unroll
            for (int c = 0; c < CC; c++)
                acc[c] += __shfl_xor_sync(0xffffffffu, acc[c], off);
        if (lane == 0) {
            float4* zr = (float4*)(Z + (size_t)row * CC);
#pragma unroll
            for (int q = 0; q < CC / 4; q++)
                zr[q] = make_float4(acc[4 * q], acc[4 * q + 1], acc[4 * q + 2], acc[4 * q + 3]);
        }
    }
}

// ---- APPNP step on 40 features: zout = 0.9 * A_hat @ zin + 0.1 * z0. warp per node ----
__global__ void __launch_bounds__(256) k_prop_appnp(
    const float* __restrict__ zin, const float* __restrict__ z0,
    float* __restrict__ zout, int n)
{
    int gw = (blockIdx.x * blockDim.x + threadIdx.x) >> 5;
    int lane = threadIdx.x & 31;
    if (gw >= n) return;
    int i = gw;
    int beg = g_off[i], end = g_off[i + 1];
    float di = g_dinv[i];
    const float* zi = zin + (size_t)i * CC;
    float a0 = di * di * __ldg(&zi[lane]);
    float a1 = (lane < 8) ? di * di * __ldg(&zi[32 + lane]) : 0.f;
    int e = beg;
    for (; e + 2 <= end; e += 2) {
        EdgeRec r0 = g_edges[e], r1 = g_edges[e + 1];
        const float* zs0 = zin + (size_t)r0.src * CC;
        const float* zs1 = zin + (size_t)r1.src * CC;
        a0 = fmaf(r0.nrm, __ldg(&zs0[lane]), a0);
        a0 = fmaf(r1.nrm, __ldg(&zs1[lane]), a0);
        if (lane < 8) {
            a1 = fmaf(r0.nrm, __ldg(&zs0[32 + lane]), a1);
            a1 = fmaf(r1.nrm, __ldg(&zs1[32 + lane]), a1);
        }
    }
    for (; e < end; e++) {
        EdgeRec r = g_edges[e];
        const float* zs = zin + (size_t)r.src * CC;
        a0 = fmaf(r.nrm, __ldg(&zs[lane]), a0);
        if (lane < 8) a1 = fmaf(r.nrm, __ldg(&zs[32 + lane]), a1);
    }
    float* zo = zout + (size_t)i * CC;
    const float* z0r = z0 + (size_t)i * CC;
    zo[lane] = 0.9f * a0 + 0.1f * __ldg(&z0r[lane]);
    if (lane < 8) zo[32 + lane] = 0.9f * a1 + 0.1f * __ldg(&z0r[32 + lane]);
}

// ---- out = log_softmax(z + fc_b). warp per row ----
__global__ void __launch_bounds__(256) k_logsoftmax(
    const float* __restrict__ Z, const float* __restrict__ b,
    float* __restrict__ out, int n)
{
    int gw = (blockIdx.x * blockDim.x + threadIdx.x) >> 5;
    int lane = threadIdx.x & 31;
    if (gw >= n) return;
    const float* zr = Z + (size_t)gw * CC;
    float v0 = zr[lane] + b[lane];
    float v1 = (lane < 8) ? zr[32 + lane] + b[32 + lane] : -1e30f;
    float m = fmaxf(v0, v1);
#pragma unroll
    for (int off = 16; off; off >>= 1)
        m = fmaxf(m, __shfl_xor_sync(0xffffffffu, m, off));
    float s = expf(v0 - m) + ((lane < 8) ? expf(v1 - m) : 0.f);
#pragma unroll
    for (int off = 16; off; off >>= 1)
        s += __shfl_xor_sync(0xffffffffu, s, off);
    float ls = m + logf(s);
    float* o = out + (size_t)gw * CC;
    o[lane] = v0 - ls;
    if (lane < 8) o[32 + lane] = v1 - ls;
}

extern "C" void kernel_launch(void* const* d_in, const int* in_sizes, int n_in,
                              void* d_out, int out_size) {
    const float* x   = (const float*)d_in[0];
    const void*  ei  = d_in[1];
    const float* w1  = (const float*)d_in[2];
    const float* b1  = (const float*)d_in[3];
    const float* w2  = (const float*)d_in[4];
    const float* b2  = (const float*)d_in[5];
    const float* w3  = (const float*)d_in[6];
    const float* b3  = (const float*)d_in[7];
    const float* fcw = (const float*)d_in[8];
    const float* fcb = (const float*)d_in[9];
    float* out = (float*)d_out;

    int n = in_sizes[0] / DD;
    int e = in_sizes[1] / 2;

    float *T, *A, *Z0, *Za, *Zb;
    cudaGetSymbolAddress((void**)&T,  g_T);
    cudaGetSymbolAddress((void**)&A,  g_A);
    cudaGetSymbolAddress((void**)&Z0, g_Z0);
    cudaGetSymbolAddress((void**)&Za, g_Za);
    cudaGetSymbolAddress((void**)&Zb, g_Zb);

    // preprocessing: dtype detect, degree, dinv, CSR build
    k_detect<<<1, 256>>>((const long long*)ei, e, n);
    k_zero_deg<<<(n + 255) / 256, 256>>>(n);
    k_hist<<<4096, 256>>>(ei, e);
    k_dinv<<<(n + 255) / 256, 256>>>(n);
    k_scan<<<1, 1024>>>(n);
    k_fill<<<4096, 256>>>(ei, e);

    // 3 GCN layers: t = h @ W; h = relu(A_hat t + b)
    dim3 gg(2, (n + 127) / 128);
    k_sgemm256<<<gg, 256>>>(x, w1, T, n);
    k_prop_gcn<<<n, 256>>>(T, b1, A, n);
    k_sgemm256<<<gg, 256>>>(A, w2, T, n);
    k_prop_gcn<<<n, 256>>>(T, b2, A, n);
    k_sgemm256<<<gg, 256>>>(A, w3, T, n);
    k_prop_gcn<<<n, 256>>>(T, b3, A, n);   // h0 in A

    // APPNP commuted with fc_w: z0 = h0 @ fc_w, then 10 steps on 40 features
    k_zgemm<<<1024, 256>>>(A, fcw, Z0, n);
    const float* cur = Z0;
    float* nxt = Za;
    for (int k = 0; k < 10; k++) {
        k_prop_appnp<<<(n + 7) / 8, 256>>>(cur, Z0, nxt, n);
        if (nxt == Za) { cur = Za; nxt = Zb; }
        else           { cur = Zb; nxt = Za; }
    }

    // logits = z + fc_b; log_softmax
    k_logsoftmax<<<(n + 7) / 8, 256>>>(cur, fcb, out, n);
}

// round 4
// speedup vs baseline: 1.1420x; 1.1420x over previous
#include <cuda_runtime.h>

#define NMAX 100000
#define EMAX 3200000
#define DD 256
#define CC 40

struct __align__(8) EdgeRec { int src; float nrm; };

// ---- static device scratch (allocation-free rule) ----
__device__ int   g_is64;
__device__ int   g_deg[NMAX];
__device__ int   g_off[NMAX + 1];
__device__ int   g_cur[NMAX];
__device__ float g_dinv[NMAX];
__device__ EdgeRec g_edges[EMAX];
__device__ float g_T [(size_t)NMAX * DD];
__device__ float g_A [(size_t)NMAX * DD];
__device__ float g_Z0[(size_t)NMAX * CC];
__device__ float g_Za[(size_t)NMAX * CC];
__device__ float g_Zb[(size_t)NMAX * CC];

// ---- dtype detection: int64 edge_index vs silently-downcast int32 ----
__global__ void k_detect(const long long* ei, int e, int n) {
    __shared__ int bad;
    if (threadIdx.x == 0) bad = 0;
    __syncthreads();
    int m = e < 2048 ? e : 2048;
    int isbad = 0;
    for (int i = threadIdx.x; i < m; i += blockDim.x) {
        long long v = ei[i];
        if (v < 0 || v >= (long long)n) isbad = 1;
    }
    if (isbad) atomicOr(&bad, 1);
    __syncthreads();
    if (threadIdx.x == 0) g_is64 = bad ? 0 : 1;
}

__global__ void k_zero_deg(int n) {
    int i = blockIdx.x * blockDim.x + threadIdx.x;
    if (i < n) g_deg[i] = 0;
}

__global__ void k_hist(const void* ei, int e) {
    int f = g_is64;
    const long long* p64 = (const long long*)ei;
    const int* p32 = (const int*)ei;
    int stride = gridDim.x * blockDim.x;
    for (int i = blockIdx.x * blockDim.x + threadIdx.x; i < e; i += stride) {
        int d = f ? (int)p64[e + i] : p32[e + i];
        atomicAdd(&g_deg[d], 1);
    }
}

__global__ void k_dinv(int n) {
    int i = blockIdx.x * blockDim.x + threadIdx.x;
    if (i < n) g_dinv[i] = rsqrtf((float)(g_deg[i] + 1));  // +1 self loop; always > 0
}

// single-block exclusive scan of g_deg -> g_off / g_cur
__global__ void k_scan(int n) {
    __shared__ int s[1024];
    int t = threadIdx.x;
    int chunk = (n + 1023) >> 10;
    int lo = t * chunk; if (lo > n) lo = n;
    int hi = lo + chunk; if (hi > n) hi = n;
    int sum = 0;
    for (int i = lo; i < hi; i++) sum += g_deg[i];
    s[t] = sum;
    __syncthreads();
    for (int off = 1; off < 1024; off <<= 1) {
        int v = 0;
        if (t >= off) v = s[t - off];
        __syncthreads();
        if (t >= off) s[t] += v;
        __syncthreads();
    }
    int run = s[t] - sum;  // exclusive prefix of this thread's chunk
    for (int i = lo; i < hi; i++) {
        g_off[i] = run; g_cur[i] = run;
        run += g_deg[i];
    }
    if (t == 0) g_off[n] = s[1023];
}

__global__ void k_fill(const void* ei, int e) {
    int f = g_is64;
    const long long* p64 = (const long long*)ei;
    const int* p32 = (const int*)ei;
    int stride = gridDim.x * blockDim.x;
    for (int i = blockIdx.x * blockDim.x + threadIdx.x; i < e; i += stride) {
        int s, d;
        if (f) { s = (int)p64[i]; d = (int)p64[e + i]; }
        else   { s = p32[i];      d = p32[e + i]; }
        int pos = atomicAdd(&g_cur[d], 1);
        EdgeRec r; r.src = s; r.nrm = g_dinv[s] * g_dinv[d];
        g_edges[pos] = r;
    }
}

// ---- SGEMM: C[M,256] = A[M,256] @ B[256,256], 128x128x8 tile, 8x8/thread,
// ---- inner product via packed fma.rn.f32x2 (FFMA2: 2x fp32 rate, exact fp32 rounding)
__global__ void __launch_bounds__(256) k_sgemm256(
    const float* __restrict__ A, const float* __restrict__ B,
    float* __restrict__ Cm, int M)
{
    __shared__ float As[8][128];
    __shared__ float Bs[8][128];
    const int tid  = threadIdx.x;
    const int trow = tid >> 4;        // 0..15
    const int tcol = tid & 15;        // 0..15
    const int aRow = tid >> 1;        // 0..127
    const int aCol = (tid & 1) * 4;   // 0 or 4
    const int bRow = tid >> 5;        // 0..7
    const int bCol = (tid & 31) * 4;  // 0..124
    const int mBase = blockIdx.y * 128;
    const int nBase = blockIdx.x * 128;
    unsigned long long accp[8][4] = {};   // 8 rows x 4 col-pairs, packed f32x2 (0ull == {0.f,0.f})
    const bool aok = (mBase + aRow) < M;
    const float* Aptr = A + (size_t)(mBase + aRow) * DD + aCol;
    const float* Bptr = B + (size_t)bRow * DD + nBase + bCol;

    for (int k0 = 0; k0 < DD; k0 += 8) {
        float4 av = make_float4(0.f, 0.f, 0.f, 0.f);
        if (aok) av = *(const float4*)(Aptr + k0);
        As[aCol + 0][aRow] = av.x;
        As[aCol + 1][aRow] = av.y;
        As[aCol + 2][aRow] = av.z;
        As[aCol + 3][aRow] = av.w;
        *(float4*)&Bs[bRow][bCol] = *(const float4*)(Bptr + (size_t)k0 * DD);
        __syncthreads();
#pragma unroll
        for (int k = 0; k < 8; k++) {
            float4 a0 = *(const float4*)&As[k][trow * 8];
            float4 a1 = *(const float4*)&As[k][trow * 8 + 4];
            // b pairs arrive pre-packed: 128-bit shared loads viewed as 2x b64
            ulonglong2 bq0 = *(const ulonglong2*)&Bs[k][tcol * 8];
            ulonglong2 bq1 = *(const ulonglong2*)&Bs[k][tcol * 8 + 4];
            unsigned long long bp[4] = {bq0.x, bq0.y, bq1.x, bq1.y};
            float ar[8] = {a0.x, a0.y, a0.z, a0.w, a1.x, a1.y, a1.z, a1.w};
#pragma unroll
            for (int i = 0; i < 8; i++) {
                unsigned long long ad;
                unsigned int ab = __float_as_uint(ar[i]);
                asm("mov.b64 %0, {%1, %1};" : "=l"(ad) : "r"(ab));
#pragma unroll
                for (int j = 0; j < 4; j++)
                    asm("fma.rn.f32x2 %0, %1, %2, %0;"
                        : "+l"(accp[i][j]) : "l"(ad), "l"(bp[j]));
            }
        }
        __syncthreads();
    }
#pragma unroll
    for (int i = 0; i < 8; i++) {
        int r = mBase + trow * 8 + i;
        if (r < M) {
            float* cp = Cm + (size_t)r * DD + nBase + tcol * 8;
            ulonglong2* cq = (ulonglong2*)cp;
            cq[0] = make_ulonglong2(accp[i][0], accp[i][1]);
            cq[1] = make_ulonglong2(accp[i][2], accp[i][3]);
        }
    }
}

// ---- GCN propagate, half-feature pass: out[:,foff:foff+128] = relu(A_hat @ tin + b)
// ---- two sequential passes keep the random-gather working set (~50MB) L2-resident
__global__ void __launch_bounds__(128) k_prop_gcn(
    const float* __restrict__ tin, const float* __restrict__ bias,
    float* __restrict__ out, int foff)
{
    int i = blockIdx.x;
    int t = foff + threadIdx.x;
    int beg = g_off[i], end = g_off[i + 1];
    float di = g_dinv[i];
    float acc0 = di * di * __ldg(&tin[(size_t)i * DD + t]);  // self loop
    float acc1 = 0.f, acc2 = 0.f, acc3 = 0.f;
    int e = beg;
    for (; e + 4 <= end; e += 4) {
        EdgeRec r0 = g_edges[e], r1 = g_edges[e + 1], r2 = g_edges[e + 2], r3 = g_edges[e + 3];
        acc0 = fmaf(r0.nrm, __ldg(&tin[(size_t)r0.src * DD + t]), acc0);
        acc1 = fmaf(r1.nrm, __ldg(&tin[(size_t)r1.src * DD + t]), acc1);
        acc2 = fmaf(r2.nrm, __ldg(&tin[(size_t)r2.src * DD + t]), acc2);
        acc3 = fmaf(r3.nrm, __ldg(&tin[(size_t)r3.src * DD + t]), acc3);
    }
    for (; e < end; e++) {
        EdgeRec r = g_edges[e];
        acc0 = fmaf(r.nrm, __ldg(&tin[(size_t)r.src * DD + t]), acc0);
    }
    float v = (acc0 + acc1) + (acc2 + acc3) + bias[t];
    out[(size_t)i * DD + t] = v > 0.f ? v : 0.f;
}

// ---- z0 = H[N,256] @ fc_w[256,40]: warp per row, W^T staged in shared ----
__global__ void __launch_bounds__(256) k_zgemm(
    const float* __restrict__ H, const float* __restrict__ W,
    float* __restrict__ Z, int n)
{
    __shared__ float wT[CC * DD];  // 40 KB, [c][k]
    for (int i = threadIdx.x; i < CC * DD; i += blockDim.x) {
        int k = i / CC, c = i - k * CC;
        wT[c * DD + k] = W[i];
    }
    __syncthreads();
    int wid = threadIdx.x >> 5, lane = threadIdx.x & 31;
    int gw = blockIdx.x * 8 + wid;
    int nw = gridDim.x * 8;
    for (int row = gw; row < n; row += nw) {
        const float* hr = H + (size_t)row * DD;
        float hv[8];
#pragma unroll
        for (int s = 0; s < 8; s++) hv[s] = __ldg(&hr[lane + 32 * s]);
        float acc[CC];
#pragma unroll
        for (int c = 0; c < CC; c++) {
            const float* wr = wT + c * DD + lane;
            float a = hv[0] * wr[0];
#pragma unroll
            for (int s = 1; s < 8; s++) a = fmaf(hv[s], wr[32 * s], a);
            acc[c] = a;
        }
#pragma unroll
        for (int off = 16; off; off >>= 1)
#pragma unroll
            for (int c = 0; c < CC; c++)
                acc[c] += __shfl_xor_sync(0xffffffffu, acc[c], off);
        if (lane == 0) {
            float4* zr = (float4*)(Z + (size_t)row * CC);
#pragma unroll
            for (int q = 0; q < CC / 4; q++)
                zr[q] = make_float4(acc[4 * q], acc[4 * q + 1], acc[4 * q + 2], acc[4 * q + 3]);
        }
    }
}

// ---- APPNP step on 40 features: zout = 0.9 * A_hat @ zin + 0.1 * z0. warp per node ----
__global__ void __launch_bounds__(256) k_prop_appnp(
    const float* __restrict__ zin, const float* __restrict__ z0,
    float* __restrict__ zout, int n)
{
    int gw = (blockIdx.x * blockDim.x + threadIdx.x) >> 5;
    int lane = threadIdx.x & 31;
    if (gw >= n) return;
    int i = gw;
    int beg = g_off[i], end = g_off[i + 1];
    float di = g_dinv[i];
    const float* zi = zin + (size_t)i * CC;
    float a0 = di * di * __ldg(&zi[lane]);
    float a1 = (lane < 8) ? di * di * __ldg(&zi[32 + lane]) : 0.f;
    int e = beg;
    for (; e + 2 <= end; e += 2) {
        EdgeRec r0 = g_edges[e], r1 = g_edges[e + 1];
        const float* zs0 = zin + (size_t)r0.src * CC;
        const float* zs1 = zin + (size_t)r1.src * CC;
        a0 = fmaf(r0.nrm, __ldg(&zs0[lane]), a0);
        a0 = fmaf(r1.nrm, __ldg(&zs1[lane]), a0);
        if (lane < 8) {
            a1 = fmaf(r0.nrm, __ldg(&zs0[32 + lane]), a1);
            a1 = fmaf(r1.nrm, __ldg(&zs1[32 + lane]), a1);
        }
    }
    for (; e < end; e++) {
        EdgeRec r = g_edges[e];
        const float* zs = zin + (size_t)r.src * CC;
        a0 = fmaf(r.nrm, __ldg(&zs[lane]), a0);
        if (lane < 8) a1 = fmaf(r.nrm, __ldg(&zs[32 + lane]), a1);
    }
    float* zo = zout + (size_t)i * CC;
    const float* z0r = z0 + (size_t)i * CC;
    zo[lane] = 0.9f * a0 + 0.1f * __ldg(&z0r[lane]);
    if (lane < 8) zo[32 + lane] = 0.9f * a1 + 0.1f * __ldg(&z0r[32 + lane]);
}

// ---- out = log_softmax(z + fc_b). warp per row ----
__global__ void __launch_bounds__(256) k_logsoftmax(
    const float* __restrict__ Z, const float* __restrict__ b,
    float* __restrict__ out, int n)
{
    int gw = (blockIdx.x * blockDim.x + threadIdx.x) >> 5;
    int lane = threadIdx.x & 31;
    if (gw >= n) return;
    const float* zr = Z + (size_t)gw * CC;
    float v0 = zr[lane] + b[lane];
    float v1 = (lane < 8) ? zr[32 + lane] + b[32 + lane] : -1e30f;
    float m = fmaxf(v0, v1);
#pragma unroll
    for (int off = 16; off; off >>= 1)
        m = fmaxf(m, __shfl_xor_sync(0xffffffffu, m, off));
    float s = expf(v0 - m) + ((lane < 8) ? expf(v1 - m) : 0.f);
#pragma unroll
    for (int off = 16; off; off >>= 1)
        s += __shfl_xor_sync(0xffffffffu, s, off);
    float ls = m + logf(s);
    float* o = out + (size_t)gw * CC;
    o[lane] = v0 - ls;
    if (lane < 8) o[32 + lane] = v1 - ls;
}

extern "C" void kernel_launch(void* const* d_in, const int* in_sizes, int n_in,
                              void* d_out, int out_size) {
    const float* x   = (const float*)d_in[0];
    const void*  ei  = d_in[1];
    const float* w1  = (const float*)d_in[2];
    const float* b1  = (const float*)d_in[3];
    const float* w2  = (const float*)d_in[4];
    const float* b2  = (const float*)d_in[5];
    const float* w3  = (const float*)d_in[6];
    const float* b3  = (const float*)d_in[7];
    const float* fcw = (const float*)d_in[8];
    const float* fcb = (const float*)d_in[9];
    float* out = (float*)d_out;

    int n = in_sizes[0] / DD;
    int e = in_sizes[1] / 2;

    float *T, *A, *Z0, *Za, *Zb;
    cudaGetSymbolAddress((void**)&T,  g_T);
    cudaGetSymbolAddress((void**)&A,  g_A);
    cudaGetSymbolAddress((void**)&Z0, g_Z0);
    cudaGetSymbolAddress((void**)&Za, g_Za);
    cudaGetSymbolAddress((void**)&Zb, g_Zb);

    // preprocessing: dtype detect, degree, dinv, CSR build
    k_detect<<<1, 256>>>((const long long*)ei, e, n);
    k_zero_deg<<<(n + 255) / 256, 256>>>(n);
    k_hist<<<4096, 256>>>(ei, e);
    k_dinv<<<(n + 255) / 256, 256>>>(n);
    k_scan<<<1, 1024>>>(n);
    k_fill<<<4096, 256>>>(ei, e);

    // 3 GCN layers: t = h @ W; h = relu(A_hat t + b)  (prop in two L2-resident half passes)
    dim3 gg(2, (n + 127) / 128);
    k_sgemm256<<<gg, 256>>>(x, w1, T, n);
    k_prop_gcn<<<n, 128>>>(T, b1, A, 0);
    k_prop_gcn<<<n, 128>>>(T, b1, A, 128);
    k_sgemm256<<<gg, 256>>>(A, w2, T, n);
    k_prop_gcn<<<n, 128>>>(T, b2, A, 0);
    k_prop_gcn<<<n, 128>>>(T, b2, A, 128);
    k_sgemm256<<<gg, 256>>>(A, w3, T, n);
    k_prop_gcn<<<n, 128>>>(T, b3, A, 0);
    k_prop_gcn<<<n, 128>>>(T, b3, A, 128);   // h0 in A

    // APPNP commuted with fc_w: z0 = h0 @ fc_w, then 10 steps on 40 features
    k_zgemm<<<1024, 256>>>(A, fcw, Z0, n);
    const float* cur = Z0;
    float* nxt = Za;
    for (int k = 0; k < 10; k++) {
        k_prop_appnp<<<(n + 7) / 8, 256>>>(cur, Z0, nxt, n);
        if (nxt == Za) { cur = Za; nxt = Zb; }
        else           { cur = Zb; nxt = Za; }
    }

    // logits = z + fc_b; log_softmax
    k_logsoftmax<<<(n + 7) / 8, 256>>>(cur, fcb, out, n);
}